// round 4
// baseline (speedup 1.0000x reference)
#include <cuda_runtime.h>

#define Bq 512
#define Tq 32
#define Nq 16384   // Tq*Bq, power of two: n = t*512 + b

// ---------------- scratch (static device arrays; no runtime alloc) ----------------
__device__ float g_xT[280 * Nq];    // [i*10+k][n] transposed local_inputs   (18.3MB)
__device__ float g_eT[4 * Nq];      // [i][n] transposed extras
__device__ float g_con[3000 * Nq];  // [k*300+j][n]                          (196MB)
__device__ float g_con1[3000 * Nq]; // [k*300+j][n]                          (196MB)
__device__ float g_ht[300 * Nq];    // [j][n]                                (19.7MB)
__device__ float g_fc1[2000 * Nq];  // [k*200+o][n]                          (131MB)
__device__ float g_sm[Tq * 10 * Bq];// [t][r][c] softmaxed wdyn
__device__ float g_u[300];          // fuse1 @ Wout
__device__ float g_v[17];           // ff^T @ Wout
__device__ float g_wA[10];          // softmax(DisM)
__device__ float g_c[2];            // biasf.Wout, bff.Wout
__device__ float g_wpT[600 * 300];  // wp transposed to [h][o]

// ---------------- helpers ----------------
__device__ __forceinline__ float sigm(float x) {
    float e = __expf(-x);
    return __fdividef(1.f, 1.f + e);
}
__device__ __forceinline__ float tanh_(float x) {
    float e = __expf(-2.f * fabsf(x));
    float t = __fdividef(1.f - e, 1.f + e);
    return copysignf(t, x);
}

// ---------------- prep: tiny precomputations ----------------
__global__ void prep_small(const float* __restrict__ DisM, const float* __restrict__ fuse1,
                           const float* __restrict__ ff, const float* __restrict__ biasf,
                           const float* __restrict__ bff, const float* __restrict__ Wout) {
    int tid = threadIdx.x;
    if (tid < 300) {
        float s = 0.f;
        for (int o = 0; o < 100; o++) s = fmaf(fuse1[tid * 100 + o], Wout[o], s);
        g_u[tid] = s;
    }
    if (tid < 17) {
        float s = 0.f;
        for (int o = 0; o < 100; o++) s = fmaf(ff[o * 17 + tid], Wout[o], s);
        g_v[tid] = s;
    }
    if (tid == 300) {
        float s = 0.f;
        for (int o = 0; o < 100; o++) s = fmaf(biasf[o], Wout[o], s);
        g_c[0] = s;
    }
    if (tid == 301) {
        float s = 0.f;
        for (int o = 0; o < 100; o++) s = fmaf(bff[o], Wout[o], s);
        g_c[1] = s;
    }
    if (tid == 302) {
        float m = DisM[0];
        for (int k = 1; k < 10; k++) m = fmaxf(m, DisM[k]);
        float e[10], d = 0.f;
        for (int k = 0; k < 10; k++) { e[k] = __expf(DisM[k] - m); d += e[k]; }
        for (int k = 0; k < 10; k++) g_wA[k] = e[k] / d;
    }
}

__global__ void prep_wpT(const float* __restrict__ wp) {
    int idx = blockIdx.x * 256 + threadIdx.x;
    if (idx < 600 * 300) {
        int h = idx / 300, o = idx - h * 300;
        g_wpT[idx] = wp[o * 600 + h];
    }
}

// ---------------- transpose inputs to [feature][n] layout ----------------
__global__ void transpose_kernel(const float* __restrict__ li, const float* __restrict__ ex) {
    int idx = blockIdx.x * 256 + threadIdx.x;
    const int total1 = 280 * Nq;
    if (idx < total1) {
        int row = idx >> 14, n = idx & (Nq - 1);
        int i = row / 10, kk = row - i * 10;
        int t = n >> 9, b = n & 511;
        g_xT[idx] = li[((b * Tq + t) * 28 + i) * 10 + kk];
    } else {
        int j = idx - total1;
        if (j < 4 * Nq) {
            int i = j >> 14, n = j & (Nq - 1);
            int t = n >> 9, b = n & 511;
            g_eT[j] = ex[(b * Tq + t) * 4 + i];
        }
    }
}

// ---------------- cells: per-neighbor zero-state LSTM cell (f gate unused) ----------------
__global__ __launch_bounds__(128) void cells_kernel(const float* __restrict__ Wih,
                                                    const float* __restrict__ b_ih,
                                                    const float* __restrict__ b_hh) {
    int n = blockIdx.x * 128 + threadIdx.x;
    int k = blockIdx.y;
    float s[11];
#pragma unroll
    for (int i = 0; i < 11; i++) s[i] = g_xT[(i * 10 + k) * Nq + n];
    const float* W = Wih + k * 13200;   // [1200][11]
    const float* bi = b_ih + k * 1200;
    const float* bh = b_hh + k * 1200;
    int outb = k * 300 * Nq + n;
    for (int j = 0; j < 300; j++) {
        float gi = bi[j] + bh[j];
        float gg = bi[600 + j] + bh[600 + j];
        float go = bi[900 + j] + bh[900 + j];
        const float* wi = W + j * 11;
        const float* wg = W + (600 + j) * 11;
        const float* wo = W + (900 + j) * 11;
#pragma unroll
        for (int i = 0; i < 11; i++) {
            gi = fmaf(wi[i], s[i], gi);
            gg = fmaf(wg[i], s[i], gg);
            go = fmaf(wo[i], s[i], go);
        }
        g_con[outb + j * Nq] = sigm(go) * tanh_(sigm(gi) * tanh_(gg));
    }
}

// ---------------- target cell ----------------
__global__ __launch_bounds__(128) void ht_kernel(const float* __restrict__ Wt,
                                                 const float* __restrict__ bti,
                                                 const float* __restrict__ bth) {
    int n = blockIdx.x * 128 + threadIdx.x;
    float e0 = g_eT[n], e1 = g_eT[Nq + n], e2 = g_eT[2 * Nq + n], e3 = g_eT[3 * Nq + n];
    for (int j = 0; j < 300; j++) {
        const float* w = Wt + j * 4;
        float gi = bti[j] + bth[j] + w[0] * e0 + w[1] * e1 + w[2] * e2 + w[3] * e3;
        w = Wt + (600 + j) * 4;
        float gg = bti[600 + j] + bth[600 + j] + w[0] * e0 + w[1] * e1 + w[2] * e2 + w[3] * e3;
        w = Wt + (900 + j) * 4;
        float go = bti[900 + j] + bth[900 + j] + w[0] * e0 + w[1] * e1 + w[2] * e2 + w[3] * e3;
        g_ht[j * Nq + n] = sigm(go) * tanh_(sigm(gi) * tanh_(gg));
    }
}

// ---------------- t=0: con1 = con directly (no wp, no relu) ----------------
__global__ void copy_t0() {
    int idx = blockIdx.x * 256 + threadIdx.x;
    if (idx < 3000 * 512) {
        int r = idx / 512, b = idx - r * 512;
        g_con1[r * Nq + b] = g_con[r * Nq + b];
    }
}

// ---------------- tiled SGEMM: MODE 0 = wp (con1), MODE 1 = F1 (fc1) ----------------
// out[o][(k,n)] = relu( sum_h A[h][o] * B[h][(k,n)] + bias[o] )
// MODE 0: M=300, cols n in [512,Nq), B rows 0..299 = con[t], 300..599 = con[t-1]
// MODE 1: M=200, cols all n,        B rows 0..299 = con1,   300..599 = ht
template <int MODE>
__global__ __launch_bounds__(320) void gemm_kernel(const float* __restrict__ A,
                                                   const float* __restrict__ bias) {
    constexpr int BM = 100, BN = 64, BK = 8;
    constexpr int Mtot = (MODE == 0) ? 300 : 200;
    const int n0 = (MODE == 0 ? 512 : 0) + blockIdx.x * BN;
    const int k = blockIdx.y;
    const int o0 = blockIdx.z * BM;
    __shared__ float As[BK][BM];
    __shared__ float Bs[BK][BN];
    const int tid = threadIdx.x;
    const int tm = tid >> 4, tn = tid & 15;  // tm 0..19, tn 0..15
    float acc[5][4];
#pragma unroll
    for (int i = 0; i < 5; i++)
#pragma unroll
        for (int j = 0; j < 4; j++) acc[i][j] = 0.f;
    const float* Ap = (MODE == 0) ? g_wpT : A;

    for (int h0 = 0; h0 < 600; h0 += BK) {
        for (int i = tid; i < BK * BM; i += 320) {
            int kk = i / BM, m = i - kk * BM;
            As[kk][m] = Ap[(h0 + kk) * Mtot + o0 + m];
        }
        for (int i = tid; i < BK * BN; i += 320) {
            int kk = i >> 6, nl = i & 63;
            int h = h0 + kk;
            float val;
            if (MODE == 0) {
                val = (h < 300) ? g_con[(k * 300 + h) * Nq + n0 + nl]
                                : g_con[(k * 300 + h - 300) * Nq + (n0 - 512) + nl];
            } else {
                val = (h < 300) ? g_con1[(k * 300 + h) * Nq + n0 + nl]
                                : g_ht[(h - 300) * Nq + n0 + nl];
            }
            Bs[kk][nl] = val;
        }
        __syncthreads();
#pragma unroll
        for (int kk = 0; kk < BK; kk++) {
            float a[5], b[4];
#pragma unroll
            for (int i = 0; i < 5; i++) a[i] = As[kk][tm * 5 + i];
            float4 bv = *reinterpret_cast<float4*>(&Bs[kk][tn * 4]);
            b[0] = bv.x; b[1] = bv.y; b[2] = bv.z; b[3] = bv.w;
#pragma unroll
            for (int i = 0; i < 5; i++)
#pragma unroll
                for (int j = 0; j < 4; j++) acc[i][j] = fmaf(a[i], b[j], acc[i][j]);
        }
        __syncthreads();
    }
#pragma unroll
    for (int i = 0; i < 5; i++) {
        int o = o0 + tm * 5 + i;
        float bv = bias[o];
#pragma unroll
        for (int j = 0; j < 4; j++) {
            int n = n0 + tn * 4 + j;
            float r = fmaxf(acc[i][j] + bv, 0.f);
            if (MODE == 0) g_con1[(k * 300 + o) * Nq + n] = r;
            else           g_fc1[(k * 200 + o) * Nq + n] = r;
        }
    }
}

// ---------------- wdyn = relu(fc2 @ F2 + b2), then the faithful softmax scramble ----------------
__global__ __launch_bounds__(256) void wdyn_kernel(const float* __restrict__ F2,
                                                   const float* __restrict__ b2,
                                                   const float* __restrict__ AngleM) {
    int n = blockIdx.x * 256 + threadIdx.x;
    int t = n >> 9, b = n & 511;
    float wd[10], mx = -1e30f;
    for (int k = 0; k < 10; k++) {
        const float* f = g_fc1 + k * 200 * Nq + n;
        float acc = b2[0];
#pragma unroll 8
        for (int o = 0; o < 200; o++) acc = fmaf(f[o * Nq], F2[o], acc);
        float fl8 = g_xT[(80 + k) * Nq + n];
        float angv = fabsf(g_xT[(100 + k) * Nq + n] - AngleM[k]) * (1.0f / 360.0f);
        acc = fmaf(fl8, F2[200], fmaf(angv, F2[201], acc));
        wd[k] = fmaxf(acc, 0.f);
        mx = fmaxf(mx, wd[k]);
    }
    float e[10], den = 0.f;
#pragma unroll
    for (int k = 0; k < 10; k++) { e[k] = __expf(wd[k] - mx); den += e[k]; }
    float inv = __fdividef(1.f, den);
    // store S[t][r][c] with r = neighbor, c = batch; scramble read happens in final
#pragma unroll
    for (int k = 0; k < 10; k++) g_sm[t * 5120 + k * 512 + b] = e[k] * inv;
}

// ---------------- final: collapsed linear tail ----------------
__global__ __launch_bounds__(256) void final_kernel(const float* __restrict__ labels,
                                                    const float* __restrict__ a,
                                                    const float* __restrict__ biasout,
                                                    float* __restrict__ out) {
    int n = blockIdx.x * 256 + threadIdx.x;
    int t = n >> 9, b = n & 511;
    float catU = 0.f;
    for (int k = 0; k < 10; k++) {
        const float* cp = g_con1 + k * 300 * Nq + n;
        float q = 0.f;
#pragma unroll 8
        for (int j = 0; j < 300; j++) q = fmaf(cp[j * Nq], g_u[j], q);
        // wa3[b,k] = S_flat[10b+k] within timestep t (faithful flat reshape)
        catU = fmaf(q, g_sm[t * 5120 + b * 10 + k], catU);
    }
    float disU = 0.f;
#pragma unroll
    for (int f = 0; f < 17; f++) {
        float s = 0.f;
#pragma unroll
        for (int k = 0; k < 10; k++) s = fmaf(g_xT[((11 + f) * 10 + k) * Nq + n], g_wA[k], s);
        disU = fmaf(s, g_v[f], disU);
    }
    float aa = a[0];
    float pred = aa * (catU + g_c[0]) + (1.f - aa) * (disU + g_c[1]) + biasout[0];
    out[n] = pred;                    // preds [T,B,1], n = t*B+b
    out[Nq + n] = labels[b * Tq + t]; // labels_r [T,B,1]
}

// ---------------- launch ----------------
extern "C" void kernel_launch(void* const* d_in, const int* in_sizes, int n_in,
                              void* d_out, int out_size) {
    const float* li      = (const float*)d_in[0];
    const float* labels  = (const float*)d_in[1];
    const float* extras  = (const float*)d_in[2];
    const float* DisM    = (const float*)d_in[3];
    const float* AngleM  = (const float*)d_in[4];
    const float* Wih     = (const float*)d_in[5];
    const float* b_ih    = (const float*)d_in[6];
    const float* b_hh    = (const float*)d_in[7];
    const float* Wt      = (const float*)d_in[8];
    const float* bt_ih   = (const float*)d_in[9];
    const float* bt_hh   = (const float*)d_in[10];
    const float* wp      = (const float*)d_in[11];
    const float* bp      = (const float*)d_in[12];
    const float* F1      = (const float*)d_in[13];
    const float* b1      = (const float*)d_in[14];
    const float* F2      = (const float*)d_in[15];
    const float* b2      = (const float*)d_in[16];
    const float* ff      = (const float*)d_in[17];
    const float* bff     = (const float*)d_in[18];
    const float* fuse1   = (const float*)d_in[19];
    const float* biasf   = (const float*)d_in[20];
    const float* Wout    = (const float*)d_in[21];
    const float* biasout = (const float*)d_in[22];
    const float* a       = (const float*)d_in[23];
    float* out = (float*)d_out;

    prep_small<<<1, 320>>>(DisM, fuse1, ff, biasf, bff, Wout);
    prep_wpT<<<(600 * 300 + 255) / 256, 256>>>(wp);
    transpose_kernel<<<284 * Nq / 256, 256>>>(li, extras);
    cells_kernel<<<dim3(Nq / 128, 10), 128>>>(Wih, b_ih, b_hh);
    ht_kernel<<<Nq / 128, 128>>>(Wt, bt_ih, bt_hh);
    copy_t0<<<3000 * 512 / 256, 256>>>();
    gemm_kernel<0><<<dim3((Nq - 512) / 64, 10, 3), 320>>>(nullptr, bp);
    gemm_kernel<1><<<dim3(Nq / 64, 10, 2), 320>>>(F1, b1);
    wdyn_kernel<<<Nq / 256, 256>>>(F2, b2, AngleM);
    final_kernel<<<Nq / 256, 256>>>(labels, a, biasout, out);
}